// round 2
// baseline (speedup 1.0000x reference)
#include <cuda_runtime.h>
#include <cuda_bf16.h>
#include <cstdint>
#include <math.h>

#define HIDDEN 2048
#define SEQ    2048
#define NH     32
#define QKV_COLS 768   // 256 q | 256 k | 256 v
#define CDIM   256     // N_HEADS * V_BITS

// ---------------- scratch (static device, no allocations) ----------------
__device__ float g_qkv[SEQ * QKV_COLS];   // tanh(q) | tanh(k) | sigmoid(v)
__device__ float g_z[SEQ * CDIM];         // emb-interpolated attention output
__device__ float g_gate[SEQ * HIDDEN];    // sigmoid(hs @ Wg^T)

// ---------------- tf32 helpers ----------------
__device__ __forceinline__ float f2tf32(float x) {
    uint32_t u;
    asm("cvt.rna.tf32.f32 %0, %1;" : "=r"(u) : "f"(x));
    return __uint_as_float(u);
}

__device__ __forceinline__ void mma8(float* c, const uint32_t* a, const uint32_t* b) {
    asm volatile(
        "mma.sync.aligned.m16n8k8.row.col.f32.tf32.tf32.f32 "
        "{%0,%1,%2,%3}, {%4,%5,%6,%7}, {%8,%9}, {%0,%1,%2,%3};\n"
        : "+f"(c[0]), "+f"(c[1]), "+f"(c[2]), "+f"(c[3])
        : "r"(a[0]), "r"(a[1]), "r"(a[2]), "r"(a[3]), "r"(b[0]), "r"(b[1]));
}

__device__ __forceinline__ float sigm(float x) { return 1.0f / (1.0f + expf(-x)); }

// swizzle key: distinct permutation per g within each bank-parity class -> conflict-free
__device__ __forceinline__ int swkey(int r) { return (r & 3) ^ ((r & 4) >> 2); }

// ---------------- GEMM (NT: C[M,N] = A[M,K] * B[N,K]^T) ----------------
// CTA tile 128x128x16, 8 warps (2x4), warp tile 64x32, m16n8k8 tf32.
constexpr int BM = 128, BN = 128, BK = 16;
constexpr int WM = 64,  WN = 32;

enum { EPI_QKV = 0, EPI_GATE = 1, EPI_OUT = 2 };

template <int EPI>
__device__ __forceinline__ void epi_store2(int row, int col, float v0, float v1,
                                           float* __restrict__ Cout) {
    if (EPI == EPI_QKV) {
        float2 y;
        if (col < 512) { y.x = tanhf(v0); y.y = tanhf(v1); }
        else           { y.x = sigm(v0);  y.y = sigm(v1);  }
        *(float2*)&g_qkv[row * QKV_COLS + col] = y;
    } else if (EPI == EPI_GATE) {
        float2 y; y.x = sigm(v0); y.y = sigm(v1);
        *(float2*)&g_gate[row * HIDDEN + col] = y;
    } else {
        float2 gt = *(const float2*)&g_gate[row * HIDDEN + col];
        float2 y; y.x = v0 * gt.x; y.y = v1 * gt.y;
        *(float2*)&Cout[row * HIDDEN + col] = y;
    }
}

template <int EPI>
__global__ __launch_bounds__(256)
void gemm_tf32(const float* __restrict__ A, int lda,
               const float* __restrict__ B0, const float* __restrict__ B1,
               const float* __restrict__ B2, int ldb, int K,
               float* __restrict__ Cout) {
    __shared__ float As[2][BM * BK];
    __shared__ float Bs[2][BN * BK];

    const int tid  = threadIdx.x;
    const int warp = tid >> 5, lane = tid & 31;
    const int g = lane >> 2, t = lane & 3;
    const int wm = warp & 1, wn = warp >> 1;      // 2 x 4 warp grid
    const int bx = blockIdx.x, by = blockIdx.y;

    const float* Ap = (EPI == EPI_OUT) ? (const float*)g_z : A;
    const float* Bp;
    int nloc;
    if (EPI == EPI_QKV) {
        if (bx < 2)      { Bp = B0; nloc = bx * BN; }
        else if (bx < 4) { Bp = B1; nloc = (bx - 2) * BN; }
        else             { Bp = B2; nloc = (bx - 4) * BN; }
    } else { Bp = B0; nloc = bx * BN; }

    // global tile load mapping: row = tid>>2 (and +64), float4 col = tid&3
    const int lr0 = tid >> 2;       // 0..63
    const int lc4 = tid & 3;        // 0..3
    const float* gA0 = Ap + (size_t)(by * BM + lr0)      * lda + lc4 * 4;
    const float* gA1 = Ap + (size_t)(by * BM + lr0 + 64) * lda + lc4 * 4;
    const float* gB0 = Bp + (size_t)(nloc + lr0)         * ldb + lc4 * 4;
    const float* gB1 = Bp + (size_t)(nloc + lr0 + 64)    * ldb + lc4 * 4;

    // smem store float4 slots (swizzled); (lr0+64) has same key (64 % 8 == 0)
    const int key0 = swkey(lr0);
    const int sa0  = (lr0 * 4 + (lc4 ^ key0)) * 4;
    const int sa1  = ((lr0 + 64) * 4 + (lc4 ^ key0)) * 4;

    float4 ra0, ra1, rb0, rb1;

    float acc[4][4][4];
#pragma unroll
    for (int i = 0; i < 4; i++)
#pragma unroll
        for (int j = 0; j < 4; j++)
#pragma unroll
            for (int l = 0; l < 4; l++) acc[i][j][l] = 0.0f;

    const int nk = K / BK;

    // prologue: load tile 0
    {
        ra0 = *(const float4*)(gA0);
        ra1 = *(const float4*)(gA1);
        rb0 = *(const float4*)(gB0);
        rb1 = *(const float4*)(gB1);
        float4 v;
        v.x = f2tf32(ra0.x); v.y = f2tf32(ra0.y); v.z = f2tf32(ra0.z); v.w = f2tf32(ra0.w);
        *(float4*)&As[0][sa0] = v;
        v.x = f2tf32(ra1.x); v.y = f2tf32(ra1.y); v.z = f2tf32(ra1.z); v.w = f2tf32(ra1.w);
        *(float4*)&As[0][sa1] = v;
        v.x = f2tf32(rb0.x); v.y = f2tf32(rb0.y); v.z = f2tf32(rb0.z); v.w = f2tf32(rb0.w);
        *(float4*)&Bs[0][sa0] = v;
        v.x = f2tf32(rb1.x); v.y = f2tf32(rb1.y); v.z = f2tf32(rb1.z); v.w = f2tf32(rb1.w);
        *(float4*)&Bs[0][sa1] = v;
    }
    __syncthreads();

    const int arow_base = wm * WM + g;          // + mt*16 (+8)
    const int brow_base = wn * WN + g;          // + nt*8
    const int kg = swkey(g);                    // rows differ from g by multiples of 8

    for (int kt = 0; kt < nk; kt++) {
        const int cur = kt & 1;
        if (kt + 1 < nk) {
            const int off = (kt + 1) * BK;
            ra0 = *(const float4*)(gA0 + off);
            ra1 = *(const float4*)(gA1 + off);
            rb0 = *(const float4*)(gB0 + off);
            rb1 = *(const float4*)(gB1 + off);
        }
#pragma unroll
        for (int ks = 0; ks < 2; ks++) {
            // k = 8*ks + t  -> float4 col (2*ks),   element t
            // k = 8*ks+t+4  -> float4 col (2*ks+1), element t
            const int c0 = (2 * ks)     ^ kg;
            const int c1 = (2 * ks + 1) ^ kg;
            uint32_t afr[4][4];
            uint32_t bfr[4][2];
#pragma unroll
            for (int mt = 0; mt < 4; mt++) {
                const int r = arow_base + mt * 16;
                const float* base = &As[cur][0];
                // a0:(r,k), a1:(r+8,k), a2:(r,k+4), a3:(r+8,k+4)
                afr[mt][0] = __float_as_uint(base[(r * 4 + c0) * 4 + t]);
                afr[mt][1] = __float_as_uint(base[((r + 8) * 4 + c0) * 4 + t]);
                afr[mt][2] = __float_as_uint(base[(r * 4 + c1) * 4 + t]);
                afr[mt][3] = __float_as_uint(base[((r + 8) * 4 + c1) * 4 + t]);
            }
#pragma unroll
            for (int nt = 0; nt < 4; nt++) {
                const int rn = brow_base + nt * 8;
                const float* base = &Bs[cur][0];
                bfr[nt][0] = __float_as_uint(base[(rn * 4 + c0) * 4 + t]);
                bfr[nt][1] = __float_as_uint(base[(rn * 4 + c1) * 4 + t]);
            }
#pragma unroll
            for (int mt = 0; mt < 4; mt++)
#pragma unroll
                for (int nt = 0; nt < 4; nt++)
                    mma8(acc[mt][nt], afr[mt], bfr[nt]);
        }
        if (kt + 1 < nk) {
            const int nxt = cur ^ 1;
            float4 v;
            v.x = f2tf32(ra0.x); v.y = f2tf32(ra0.y); v.z = f2tf32(ra0.z); v.w = f2tf32(ra0.w);
            *(float4*)&As[nxt][sa0] = v;
            v.x = f2tf32(ra1.x); v.y = f2tf32(ra1.y); v.z = f2tf32(ra1.z); v.w = f2tf32(ra1.w);
            *(float4*)&As[nxt][sa1] = v;
            v.x = f2tf32(rb0.x); v.y = f2tf32(rb0.y); v.z = f2tf32(rb0.z); v.w = f2tf32(rb0.w);
            *(float4*)&Bs[nxt][sa0] = v;
            v.x = f2tf32(rb1.x); v.y = f2tf32(rb1.y); v.z = f2tf32(rb1.z); v.w = f2tf32(rb1.w);
            *(float4*)&Bs[nxt][sa1] = v;
        }
        __syncthreads();
    }

    // epilogue: c0:(row,2t), c1:(row,2t+1), c2:(row+8,2t), c3:(row+8,2t+1)
#pragma unroll
    for (int mt = 0; mt < 4; mt++) {
#pragma unroll
        for (int nt = 0; nt < 4; nt++) {
            const int row = by * BM + wm * WM + mt * 16 + g;
            const int col = bx * BN + wn * WN + nt * 8 + 2 * t;
            const float* c = acc[mt][nt];
            epi_store2<EPI>(row,     col, c[0], c[1], Cout);
            epi_store2<EPI>(row + 8, col, c[2], c[3], Cout);
        }
    }
}

// ---------------- windowed decayed-softmax attention ----------------
// decay 0.45 => bias -0.7985*dist; truncation at W=64 leaves < 1e-21 relative mass.
constexpr int WIN = 64, QB = 128;
constexpr int SROWS = QB + WIN - 1;   // 191
constexpr int PITCH = 9;              // conflict-free scalar smem reads

__global__ __launch_bounds__(128)
void attn_kernel(const float* __restrict__ e0, const float* __restrict__ e1) {
    __shared__ float ks[SROWS * PITCH];
    __shared__ float vs[SROWS * PITCH];

    const int h   = blockIdx.y;
    const int q0  = blockIdx.x * QB;
    const int tid = threadIdx.x;
    const int j0  = q0 - (WIN - 1);

    for (int idx = tid; idx < SROWS * 8; idx += 128) {
        const int r = idx >> 3, c = idx & 7;
        const int j = j0 + r;
        float kv = 0.0f, vv = 0.0f;
        if (j >= 0) {
            kv = g_qkv[j * QKV_COLS + 256 + h * 8 + c];
            vv = g_qkv[j * QKV_COLS + 512 + h * 8 + c];
        }
        ks[r * PITCH + c] = kv;
        vs[r * PITCH + c] = vv;
    }
    __syncthreads();

    const int i = q0 + tid;
    float q[8];
#pragma unroll
    for (int b = 0; b < 8; b++) q[b] = g_qkv[i * QKV_COLS + h * 8 + b];

    float num[8];
#pragma unroll
    for (int b = 0; b < 8; b++) num[b] = 0.0f;
    float den = 0.0f;

    const float LOGD = -0.7985077f;   // ln(0.45)
    const int dmax = (i < WIN - 1) ? i : (WIN - 1);

    for (int d = 0; d <= dmax; d++) {
        const int jj = (tid + (WIN - 1) - d) * PITCH;
        float dot = 0.0f;
#pragma unroll
        for (int b = 0; b < 8; b++) dot += q[b] * ks[jj + b];
        const float w = expf(dot * 0.125f + (float)d * LOGD);
        den += w;
#pragma unroll
        for (int b = 0; b < 8; b++) num[b] += w * vs[jj + b];
    }

    const float inv = 1.0f / den;
#pragma unroll
    for (int b = 0; b < 8; b++) {
        const int c = h * 8 + b;
        const float p = num[b] * inv;
        g_z[i * CDIM + c] = e1[c] * p + e0[c] * (1.0f - p);
    }
}

// ---------------- launch ----------------
extern "C" void kernel_launch(void* const* d_in, const int* in_sizes, int n_in,
                              void* d_out, int out_size) {
    const float* hs = (const float*)d_in[0];
    const float* Wq = (const float*)d_in[1];
    const float* Wk = (const float*)d_in[2];
    const float* Wv = (const float*)d_in[3];
    const float* Wo = (const float*)d_in[4];
    const float* Wg = (const float*)d_in[5];
    const float* e0 = (const float*)d_in[6];
    const float* e1 = (const float*)d_in[7];
    float* out = (float*)d_out;

    // 1) QKV projections + activations  (M=2048, N=768, K=2048)
    gemm_tf32<EPI_QKV><<<dim3(QKV_COLS / BN, SEQ / BM), 256>>>(
        hs, HIDDEN, Wq, Wk, Wv, HIDDEN, HIDDEN, nullptr);

    // 2) windowed attention + value-embedding interpolation
    attn_kernel<<<dim3(SEQ / QB, NH), 128>>>(e0, e1);

    // 3) gate = sigmoid(hs @ Wg^T)  (M=2048, N=2048, K=2048)
    gemm_tf32<EPI_GATE><<<dim3(HIDDEN / BN, SEQ / BM), 256>>>(
        hs, HIDDEN, Wg, Wg, Wg, HIDDEN, HIDDEN, nullptr);

    // 4) out = (z @ Wo^T) * gate  (M=2048, N=2048, K=256)
    gemm_tf32<EPI_OUT><<<dim3(HIDDEN / BN, SEQ / BM), 256>>>(
        nullptr, CDIM, Wo, Wo, Wo, CDIM, CDIM, out);
}

// round 3
// speedup vs baseline: 1.2752x; 1.2752x over previous
#include <cuda_runtime.h>
#include <cuda_bf16.h>
#include <cstdint>
#include <math.h>

#define HIDDEN 2048
#define SEQ    2048
#define NH     32
#define QKV_COLS 768   // 256 q | 256 k | 256 v
#define CDIM   256     // N_HEADS * V_BITS

// ---------------- scratch (static device, no allocations) ----------------
__device__ float g_qkv[SEQ * QKV_COLS];   // tanh(q) | tanh(k) | sigmoid(v)
__device__ float g_z[SEQ * CDIM];         // emb-interpolated attention output
__device__ float g_gate[SEQ * HIDDEN];    // sigmoid(hs @ Wg^T)

// ---------------- helpers ----------------
__device__ __forceinline__ float f2tf32(float x) {
    uint32_t u;
    asm("cvt.rna.tf32.f32 %0, %1;" : "=r"(u) : "f"(x));
    return __uint_as_float(u);
}

__device__ __forceinline__ void mma8(float* c, const uint32_t* a, const uint32_t* b) {
    asm volatile(
        "mma.sync.aligned.m16n8k8.row.col.f32.tf32.tf32.f32 "
        "{%0,%1,%2,%3}, {%4,%5,%6,%7}, {%8,%9}, {%0,%1,%2,%3};\n"
        : "+f"(c[0]), "+f"(c[1]), "+f"(c[2]), "+f"(c[3])
        : "r"(a[0]), "r"(a[1]), "r"(a[2]), "r"(a[3]), "r"(b[0]), "r"(b[1]));
}

__device__ __forceinline__ void ldsm4(uint32_t* d, uint32_t addr) {
    asm volatile("ldmatrix.sync.aligned.m8n8.x4.shared.b16 {%0,%1,%2,%3}, [%4];"
                 : "=r"(d[0]), "=r"(d[1]), "=r"(d[2]), "=r"(d[3]) : "r"(addr));
}

__device__ __forceinline__ float sigm(float x) { return 1.0f / (1.0f + expf(-x)); }

// swizzle key: distinct permutation per row within each bank-parity class -> conflict-free
__device__ __forceinline__ int swkey(int r) { return (r & 3) ^ ((r & 4) >> 2); }

// ---------------- GEMM (NT: C[M,N] = A[M,K] * B[N,K]^T) ----------------
// CTA tile 128x128x16, 8 warps (2x4), warp tile 64x32, m16n8k8 tf32.
constexpr int BM = 128, BN = 128, BK = 16;
constexpr int WM = 64,  WN = 32;
constexpr int BUFB = BM * BK * 4;   // bytes per smem buffer (A or B)

enum { EPI_QKV = 0, EPI_GATE = 1, EPI_OUT = 2 };

// Shared mainloop: accumulates C tile; caller handles epilogue.
// acc layout: acc[mt][nt][4]
__device__ __forceinline__ void gemm_mainloop(
    float (*As)[BM * BK], float (*Bs)[BN * BK],
    const float* __restrict__ Ap, int lda,
    const float* __restrict__ Bp, int ldb,
    int mloc, int nloc, int K, float acc[4][4][4]) {

    const int tid  = threadIdx.x;
    const int warp = tid >> 5, lane = tid & 31;
    const int wm = warp & 1, wn = warp >> 1;

    // ---- producer mapping ----
    const int lr0 = tid >> 2;       // 0..63
    const int lc4 = tid & 3;        // 0..3
    const float* gA0 = Ap + (size_t)(mloc + lr0)      * lda + lc4 * 4;
    const float* gA1 = Ap + (size_t)(mloc + lr0 + 64) * lda + lc4 * 4;
    const float* gB0 = Bp + (size_t)(nloc + lr0)      * ldb + lc4 * 4;
    const float* gB1 = Bp + (size_t)(nloc + lr0 + 64) * ldb + lc4 * 4;
    const int key0 = swkey(lr0);
    const int sa0  = (lr0 * 4 + (lc4 ^ key0)) * 4;
    const int sa1  = ((lr0 + 64) * 4 + (lc4 ^ key0)) * 4;

    // ---- consumer (ldmatrix) lane addressing ----
    const int l7   = lane & 7;
    const int keyl = swkey(l7);
    const uint32_t sA = (uint32_t)__cvta_generic_to_shared(&As[0][0]);
    const uint32_t sB = (uint32_t)__cvta_generic_to_shared(&Bs[0][0]);
    // A x4: matrices {rows r..r+7 @c0, r+8..r+15 @c0, r..r+7 @c1, r+8..r+15 @c1}
    const int a_row = l7 + ((lane >> 3) & 1) * 8;
    const int a_hb  = lane >> 4;              // 0 -> c0, 1 -> c1
    // B x4 (nt pair): {n..n+7 @c0, n..n+7 @c1, n+8..n+15 @c0, n+8..n+15 @c1}
    const int b_row = l7 + (lane >> 4) * 8;
    const int b_hb  = (lane >> 3) & 1;
    uint32_t aBase[4], bBase[2];
#pragma unroll
    for (int mt = 0; mt < 4; mt++)
        aBase[mt] = sA + (uint32_t)((wm * WM + mt * 16 + a_row) * 64);
#pragma unroll
    for (int p = 0; p < 2; p++)
        bBase[p] = sB + (uint32_t)((wn * WN + p * 16 + b_row) * 64);

    float4 ra0, ra1, rb0, rb1;
    const int nk = K / BK;

    // prologue: tile 0
    {
        ra0 = *(const float4*)(gA0);
        ra1 = *(const float4*)(gA1);
        rb0 = *(const float4*)(gB0);
        rb1 = *(const float4*)(gB1);
        float4 v;
        v.x = f2tf32(ra0.x); v.y = f2tf32(ra0.y); v.z = f2tf32(ra0.z); v.w = f2tf32(ra0.w);
        *(float4*)&As[0][sa0] = v;
        v.x = f2tf32(ra1.x); v.y = f2tf32(ra1.y); v.z = f2tf32(ra1.z); v.w = f2tf32(ra1.w);
        *(float4*)&As[0][sa1] = v;
        v.x = f2tf32(rb0.x); v.y = f2tf32(rb0.y); v.z = f2tf32(rb0.z); v.w = f2tf32(rb0.w);
        *(float4*)&Bs[0][sa0] = v;
        v.x = f2tf32(rb1.x); v.y = f2tf32(rb1.y); v.z = f2tf32(rb1.z); v.w = f2tf32(rb1.w);
        *(float4*)&Bs[0][sa1] = v;
    }
    __syncthreads();

    for (int kt = 0; kt < nk; kt++) {
        const int cur = kt & 1;
        const uint32_t abuf = (uint32_t)(cur * BUFB);
        if (kt + 1 < nk) {
            const int off = (kt + 1) * BK;
            ra0 = *(const float4*)(gA0 + off);
            ra1 = *(const float4*)(gA1 + off);
            rb0 = *(const float4*)(gB0 + off);
            rb1 = *(const float4*)(gB1 + off);
        }
#pragma unroll
        for (int ks = 0; ks < 2; ks++) {
            uint32_t afr[4][4];
            uint32_t bfr[2][4];
            const uint32_t aslot = (uint32_t)(((2 * ks + a_hb) ^ keyl) * 16);
            const uint32_t bslot = (uint32_t)(((2 * ks + b_hb) ^ keyl) * 16);
#pragma unroll
            for (int mt = 0; mt < 4; mt++)
                ldsm4(afr[mt], aBase[mt] + abuf + aslot);
#pragma unroll
            for (int p = 0; p < 2; p++)
                ldsm4(bfr[p], bBase[p] + abuf + bslot);
#pragma unroll
            for (int mt = 0; mt < 4; mt++)
#pragma unroll
                for (int nt = 0; nt < 4; nt++)
                    mma8(acc[mt][nt], afr[mt], &bfr[nt >> 1][(nt & 1) * 2]);
        }
        if (kt + 1 < nk) {
            const int nxt = cur ^ 1;
            float4 v;
            v.x = f2tf32(ra0.x); v.y = f2tf32(ra0.y); v.z = f2tf32(ra0.z); v.w = f2tf32(ra0.w);
            *(float4*)&As[nxt][sa0] = v;
            v.x = f2tf32(ra1.x); v.y = f2tf32(ra1.y); v.z = f2tf32(ra1.z); v.w = f2tf32(ra1.w);
            *(float4*)&As[nxt][sa1] = v;
            v.x = f2tf32(rb0.x); v.y = f2tf32(rb0.y); v.z = f2tf32(rb0.z); v.w = f2tf32(rb0.w);
            *(float4*)&Bs[nxt][sa0] = v;
            v.x = f2tf32(rb1.x); v.y = f2tf32(rb1.y); v.z = f2tf32(rb1.z); v.w = f2tf32(rb1.w);
            *(float4*)&Bs[nxt][sa1] = v;
        }
        __syncthreads();
    }
}

// ---- fused QKV + GATE kernel: 256 GATE CTAs + 96 QKV CTAs in one launch ----
__global__ __launch_bounds__(256, 2)
void gemm_qkv_gate(const float* __restrict__ hs,
                   const float* __restrict__ Wq, const float* __restrict__ Wk,
                   const float* __restrict__ Wv, const float* __restrict__ Wg) {
    __shared__ float As[2][BM * BK];
    __shared__ float Bs[2][BN * BK];

    const int cid = blockIdx.x;
    const float* Bp;
    int nloc, mloc, epi;
    if (cid < 256) {                 // GATE: 16 x 16 tiles
        epi = EPI_GATE;
        nloc = (cid & 15) * BN;
        mloc = (cid >> 4) * BM;
        Bp = Wg;
    } else {                          // QKV: 6 x 16 tiles
        epi = EPI_QKV;
        const int r = cid - 256;
        const int bx = r % 6;
        mloc = (r / 6) * BM;
        if (bx < 2)      { Bp = Wq; nloc = bx * BN; }
        else if (bx < 4) { Bp = Wk; nloc = (bx - 2) * BN; }
        else             { Bp = Wv; nloc = (bx - 4) * BN; }
    }

    float acc[4][4][4];
#pragma unroll
    for (int i = 0; i < 4; i++)
#pragma unroll
        for (int j = 0; j < 4; j++)
#pragma unroll
            for (int l = 0; l < 4; l++) acc[i][j][l] = 0.0f;

    gemm_mainloop(As, Bs, hs, HIDDEN, Bp, HIDDEN, mloc, nloc, HIDDEN, acc);

    const int tid = threadIdx.x;
    const int warp = tid >> 5, lane = tid & 31;
    const int g = lane >> 2, t = lane & 3;
    const int wm = warp & 1, wn = warp >> 1;

#pragma unroll
    for (int mt = 0; mt < 4; mt++) {
#pragma unroll
        for (int nt = 0; nt < 4; nt++) {
            const int row0 = mloc + wm * WM + mt * 16 + g;
            const int coln = wn * WN + nt * 8 + 2 * t;     // 0..127 within tile
            const float* c = acc[mt][nt];
            if (epi == EPI_GATE) {
                const int col = nloc + coln;
                float2 y0, y1;
                y0.x = sigm(c[0]); y0.y = sigm(c[1]);
                y1.x = sigm(c[2]); y1.y = sigm(c[3]);
                *(float2*)&g_gate[row0 * HIDDEN + col] = y0;
                *(float2*)&g_gate[(row0 + 8) * HIDDEN + col] = y1;
            } else {
                const int col = nloc + coln;   // column within this weight's 256-block base
                // recover global qkv column: Bp selection already fixed the 256-block;
                // nloc is 0 or 128 within that block. Compute global col:
                // handled below via base offset passed through nloc/Bp mapping.
                // We instead recompute: EPI_QKV writes into g_qkv at qcol.
                // qcol = (block base) + col. Block base: Wq->0, Wk->256, Wv->512.
                // We encode it by comparing pointers is ugly; recompute from blockIdx:
                const int r = blockIdx.x - 256;
                const int bx = r % 6;
                const int qbase = (bx >> 1) * 256;          // 0,256,512
                const int qcol = qbase + (bx & 1) * BN + coln;
                float2 y0, y1;
                if (qbase < 512) {
                    y0.x = tanhf(c[0]); y0.y = tanhf(c[1]);
                    y1.x = tanhf(c[2]); y1.y = tanhf(c[3]);
                } else {
                    y0.x = sigm(c[0]); y0.y = sigm(c[1]);
                    y1.x = sigm(c[2]); y1.y = sigm(c[3]);
                }
                *(float2*)&g_qkv[row0 * QKV_COLS + qcol] = y0;
                *(float2*)&g_qkv[(row0 + 8) * QKV_COLS + qcol] = y1;
                (void)col;
            }
        }
    }
}

// ---- OUT kernel: out = (z @ Wo^T) * gate ----
__global__ __launch_bounds__(256, 2)
void gemm_out(const float* __restrict__ Wo, float* __restrict__ Cout) {
    __shared__ float As[2][BM * BK];
    __shared__ float Bs[2][BN * BK];

    const int nloc = (blockIdx.x & 15) * BN;
    const int mloc = (blockIdx.x >> 4) * BM;

    float acc[4][4][4];
#pragma unroll
    for (int i = 0; i < 4; i++)
#pragma unroll
        for (int j = 0; j < 4; j++)
#pragma unroll
            for (int l = 0; l < 4; l++) acc[i][j][l] = 0.0f;

    gemm_mainloop(As, Bs, (const float*)g_z, CDIM, Wo, CDIM, mloc, nloc, CDIM, acc);

    const int tid = threadIdx.x;
    const int warp = tid >> 5, lane = tid & 31;
    const int g = lane >> 2, t = lane & 3;
    const int wm = warp & 1, wn = warp >> 1;

#pragma unroll
    for (int mt = 0; mt < 4; mt++) {
#pragma unroll
        for (int nt = 0; nt < 4; nt++) {
            const int row0 = mloc + wm * WM + mt * 16 + g;
            const int col  = nloc + wn * WN + nt * 8 + 2 * t;
            const float* c = acc[mt][nt];
            float2 gt0 = *(const float2*)&g_gate[row0 * HIDDEN + col];
            float2 gt1 = *(const float2*)&g_gate[(row0 + 8) * HIDDEN + col];
            float2 y0, y1;
            y0.x = c[0] * gt0.x; y0.y = c[1] * gt0.y;
            y1.x = c[2] * gt1.x; y1.y = c[3] * gt1.y;
            *(float2*)&Cout[row0 * HIDDEN + col] = y0;
            *(float2*)&Cout[(row0 + 8) * HIDDEN + col] = y1;
        }
    }
}

// ---------------- windowed decayed-softmax attention ----------------
// decay 0.45 => bias -0.7985*dist; truncation at W=64 leaves < 1e-21 relative mass.
constexpr int WIN = 64, QB = 128;
constexpr int SROWS = QB + WIN - 1;   // 191
constexpr int PITCH = 9;              // conflict-free scalar smem reads

__global__ __launch_bounds__(128)
void attn_kernel(const float* __restrict__ e0, const float* __restrict__ e1) {
    __shared__ float ks[SROWS * PITCH];
    __shared__ float vs[SROWS * PITCH];

    const int h   = blockIdx.y;
    const int q0  = blockIdx.x * QB;
    const int tid = threadIdx.x;
    const int j0  = q0 - (WIN - 1);

    for (int idx = tid; idx < SROWS * 8; idx += 128) {
        const int r = idx >> 3, c = idx & 7;
        const int j = j0 + r;
        float kv = 0.0f, vv = 0.0f;
        if (j >= 0) {
            kv = g_qkv[j * QKV_COLS + 256 + h * 8 + c];
            vv = g_qkv[j * QKV_COLS + 512 + h * 8 + c];
        }
        ks[r * PITCH + c] = kv;
        vs[r * PITCH + c] = vv;
    }
    __syncthreads();

    const int i = q0 + tid;
    float q[8];
#pragma unroll
    for (int b = 0; b < 8; b++) q[b] = g_qkv[i * QKV_COLS + h * 8 + b];

    float num[8];
#pragma unroll
    for (int b = 0; b < 8; b++) num[b] = 0.0f;
    float den = 0.0f;

    const float LOGD = -0.7985077f;   // ln(0.45)
    const int dmax = (i < WIN - 1) ? i : (WIN - 1);

    for (int d = 0; d <= dmax; d++) {
        const int jj = (tid + (WIN - 1) - d) * PITCH;
        float dot = 0.0f;
#pragma unroll
        for (int b = 0; b < 8; b++) dot += q[b] * ks[jj + b];
        const float w = expf(dot * 0.125f + (float)d * LOGD);
        den += w;
#pragma unroll
        for (int b = 0; b < 8; b++) num[b] += w * vs[jj + b];
    }

    const float inv = 1.0f / den;
#pragma unroll
    for (int b = 0; b < 8; b++) {
        const int c = h * 8 + b;
        const float p = num[b] * inv;
        g_z[i * CDIM + c] = e1[c] * p + e0[c] * (1.0f - p);
    }
}

// ---------------- launch ----------------
extern "C" void kernel_launch(void* const* d_in, const int* in_sizes, int n_in,
                              void* d_out, int out_size) {
    const float* hs = (const float*)d_in[0];
    const float* Wq = (const float*)d_in[1];
    const float* Wk = (const float*)d_in[2];
    const float* Wv = (const float*)d_in[3];
    const float* Wo = (const float*)d_in[4];
    const float* Wg = (const float*)d_in[5];
    const float* e0 = (const float*)d_in[6];
    const float* e1 = (const float*)d_in[7];
    float* out = (float*)d_out;

    // 1) fused QKV projections (+activations) and gate GEMM (+sigmoid)
    gemm_qkv_gate<<<256 + 96, 256>>>(hs, Wq, Wk, Wv, Wg);

    // 2) windowed attention + value-embedding interpolation
    attn_kernel<<<dim3(SEQ / QB, NH), 128>>>(e0, e1);

    // 3) out = (z @ Wo^T) * gate
    gemm_out<<<256, 256>>>(Wo, out);
}

// round 5
// speedup vs baseline: 1.5777x; 1.2372x over previous
#include <cuda_runtime.h>
#include <cuda_bf16.h>
#include <cstdint>
#include <math.h>

#define HIDDEN 2048
#define SEQ    2048
#define NH     32
#define QKV_COLS 768   // 256 q | 256 k | 256 v
#define CDIM   256     // N_HEADS * V_BITS

// ---------------- scratch (static device, no allocations) ----------------
__device__ float g_qkv[SEQ * QKV_COLS];     // tanh(q) | tanh(k) | sigmoid(v)
__device__ float g_z[SEQ * CDIM];           // emb-interpolated attn out (tf32-rounded)
__device__ float g_gate[SEQ * HIDDEN];      // sigmoid(hs @ Wg^T)
// tf32-prerounded copies of GEMM inputs
__device__ float g_hsr[SEQ * HIDDEN];
__device__ float g_wgr[HIDDEN * HIDDEN];
__device__ float g_wqkvr[QKV_COLS * HIDDEN];  // Wq | Wk | Wv concatenated
__device__ float g_wor[HIDDEN * CDIM];

// ---------------- helpers ----------------
__device__ __forceinline__ float f2tf32(float x) {
    uint32_t u;
    asm("cvt.rna.tf32.f32 %0, %1;" : "=r"(u) : "f"(x));
    return __uint_as_float(u);
}

__device__ __forceinline__ void mma8(float* c, const uint32_t* a, const uint32_t* b) {
    asm volatile(
        "mma.sync.aligned.m16n8k8.row.col.f32.tf32.tf32.f32 "
        "{%0,%1,%2,%3}, {%4,%5,%6,%7}, {%8,%9}, {%0,%1,%2,%3};\n"
        : "+f"(c[0]), "+f"(c[1]), "+f"(c[2]), "+f"(c[3])
        : "r"(a[0]), "r"(a[1]), "r"(a[2]), "r"(a[3]), "r"(b[0]), "r"(b[1]));
}

__device__ __forceinline__ void ldsm4(uint32_t* d, uint32_t addr) {
    asm volatile("ldmatrix.sync.aligned.m8n8.x4.shared.b16 {%0,%1,%2,%3}, [%4];"
                 : "=r"(d[0]), "=r"(d[1]), "=r"(d[2]), "=r"(d[3]) : "r"(addr));
}

__device__ __forceinline__ void cp16(uint32_t dst, const void* src) {
    asm volatile("cp.async.cg.shared.global [%0], [%1], 16;" :: "r"(dst), "l"(src));
}
__device__ __forceinline__ void cp_commit() { asm volatile("cp.async.commit_group;"); }
template <int N>
__device__ __forceinline__ void cp_wait() { asm volatile("cp.async.wait_group %0;" :: "n"(N)); }

__device__ __forceinline__ float sigm(float x) { return 1.0f / (1.0f + expf(-x)); }

// swizzle key: distinct permutation per row within each bank-parity class -> conflict-free
__device__ __forceinline__ int swkey(int r) { return (r & 3) ^ ((r & 4) >> 2); }

// ---------------- GEMM (NT: C[M,N] = A[M,K] * B[N,K]^T) ----------------
// CTA tile 128x128x16, 8 warps (2x4), warp tile 64x32, m16n8k8 tf32.
// 3-stage cp.async pipeline; inputs already tf32-rounded.
constexpr int BM = 128, BN = 128, BK = 16;
constexpr int WM = 64,  WN = 32;
constexpr int STAGEB = BM * BK * 4;   // 8192 bytes per stage per operand

__device__ __forceinline__ void gemm_mainloop(
    float (*As)[BM * BK], float (*Bs)[BN * BK],
    const float* __restrict__ Ap, int lda,
    const float* __restrict__ Bp, int ldb,
    int mloc, int nloc, int K, float acc[4][4][4]) {

    const int tid  = threadIdx.x;
    const int warp = tid >> 5, lane = tid & 31;
    const int wm = warp & 1, wn = warp >> 1;

    // ---- producer mapping ----
    const int lr0 = tid >> 2;       // 0..63
    const int lc4 = tid & 3;        // 0..3
    const float* gA0 = Ap + (size_t)(mloc + lr0)      * lda + lc4 * 4;
    const float* gA1 = Ap + (size_t)(mloc + lr0 + 64) * lda + lc4 * 4;
    const float* gB0 = Bp + (size_t)(nloc + lr0)      * ldb + lc4 * 4;
    const float* gB1 = Bp + (size_t)(nloc + lr0 + 64) * ldb + lc4 * 4;
    const int key0 = swkey(lr0);
    const uint32_t sAb = (uint32_t)__cvta_generic_to_shared(&As[0][0]);
    const uint32_t sBb = (uint32_t)__cvta_generic_to_shared(&Bs[0][0]);
    const uint32_t sa0 = (uint32_t)((lr0 * 4 + (lc4 ^ key0)) * 16);
    const uint32_t sa1 = (uint32_t)(((lr0 + 64) * 4 + (lc4 ^ key0)) * 16);

    // ---- consumer (ldmatrix) lane addressing ----
    const int l7   = lane & 7;
    const int keyl = swkey(l7);
    const int a_row = l7 + ((lane >> 3) & 1) * 8;
    const int a_hb  = lane >> 4;
    const int b_row = l7 + (lane >> 4) * 8;
    const int b_hb  = (lane >> 3) & 1;
    uint32_t aBase[4], bBase[2];
#pragma unroll
    for (int mt = 0; mt < 4; mt++)
        aBase[mt] = sAb + (uint32_t)((wm * WM + mt * 16 + a_row) * 64);
#pragma unroll
    for (int p = 0; p < 2; p++)
        bBase[p] = sBb + (uint32_t)((wn * WN + p * 16 + b_row) * 64);

    const int nk = K / BK;

    // prologue: tiles 0,1 into stages 0,1
#pragma unroll
    for (int p = 0; p < 2; p++) {
        const int off = p * BK;
        const uint32_t sb = (uint32_t)(p * STAGEB);
        cp16(sAb + sb + sa0, gA0 + off);
        cp16(sAb + sb + sa1, gA1 + off);
        cp16(sBb + sb + sa0, gB0 + off);
        cp16(sBb + sb + sa1, gB1 + off);
        cp_commit();
    }

    int st = 0;
    for (int kt = 0; kt < nk; kt++) {
        cp_wait<1>();
        __syncthreads();
        const uint32_t abuf = (uint32_t)(st * STAGEB);
#pragma unroll
        for (int ks = 0; ks < 2; ks++) {
            uint32_t afr[4][4];
            uint32_t bfr[2][4];
            const uint32_t aslot = (uint32_t)(((2 * ks + a_hb) ^ keyl) * 16);
            const uint32_t bslot = (uint32_t)(((2 * ks + b_hb) ^ keyl) * 16);
#pragma unroll
            for (int mt = 0; mt < 4; mt++)
                ldsm4(afr[mt], aBase[mt] + abuf + aslot);
#pragma unroll
            for (int p = 0; p < 2; p++)
                ldsm4(bfr[p], bBase[p] + abuf + bslot);
#pragma unroll
            for (int mt = 0; mt < 4; mt++)
#pragma unroll
                for (int nt = 0; nt < 4; nt++)
                    mma8(acc[mt][nt], afr[mt], &bfr[nt >> 1][(nt & 1) * 2]);
        }
        if (kt + 2 < nk) {
            int stp = st + 2; if (stp >= 3) stp -= 3;
            const int off = (kt + 2) * BK;
            const uint32_t sb = (uint32_t)(stp * STAGEB);
            cp16(sAb + sb + sa0, gA0 + off);
            cp16(sAb + sb + sa1, gA1 + off);
            cp16(sBb + sb + sa0, gB0 + off);
            cp16(sBb + sb + sa1, gB1 + off);
        }
        cp_commit();
        if (++st == 3) st = 0;
    }
}

// ---- fused QKV + GATE kernel ----
__global__ __launch_bounds__(256, 2)
void gemm_qkv_gate() {
    __shared__ float As[3][BM * BK];
    __shared__ float Bs[3][BN * BK];

    const int cid = blockIdx.x;
    const float* Bp;
    int nloc, mloc;
    bool is_gate;
    if (cid < 256) {                  // GATE: 16 x 16 tiles
        is_gate = true;
        nloc = (cid & 15) * BN;
        mloc = (cid >> 4) * BM;
        Bp = g_wgr;
    } else {                          // QKV: 6 x 16 tiles over concat [768,2048]
        is_gate = false;
        const int r = cid - 256;
        nloc = (r % 6) * BN;
        mloc = (r / 6) * BM;
        Bp = g_wqkvr;
    }

    float acc[4][4][4];
#pragma unroll
    for (int i = 0; i < 4; i++)
#pragma unroll
        for (int j = 0; j < 4; j++)
#pragma unroll
            for (int l = 0; l < 4; l++) acc[i][j][l] = 0.0f;

    gemm_mainloop(As, Bs, g_hsr, HIDDEN, Bp, HIDDEN, mloc, nloc, HIDDEN, acc);

    const int tid = threadIdx.x;
    const int warp = tid >> 5, lane = tid & 31;
    const int g = lane >> 2, t = lane & 3;
    const int wm = warp & 1, wn = warp >> 1;

#pragma unroll
    for (int mt = 0; mt < 4; mt++) {
#pragma unroll
        for (int nt = 0; nt < 4; nt++) {
            const int row0 = mloc + wm * WM + mt * 16 + g;
            const int col  = nloc + wn * WN + nt * 8 + 2 * t;
            const float* c = acc[mt][nt];
            if (is_gate) {
                float2 y0, y1;
                y0.x = sigm(c[0]); y0.y = sigm(c[1]);
                y1.x = sigm(c[2]); y1.y = sigm(c[3]);
                *(float2*)&g_gate[row0 * HIDDEN + col] = y0;
                *(float2*)&g_gate[(row0 + 8) * HIDDEN + col] = y1;
            } else {
                float2 y0, y1;
                if (col < 512) {
                    y0.x = tanhf(c[0]); y0.y = tanhf(c[1]);
                    y1.x = tanhf(c[2]); y1.y = tanhf(c[3]);
                } else {
                    y0.x = sigm(c[0]); y0.y = sigm(c[1]);
                    y1.x = sigm(c[2]); y1.y = sigm(c[3]);
                }
                *(float2*)&g_qkv[row0 * QKV_COLS + col] = y0;
                *(float2*)&g_qkv[(row0 + 8) * QKV_COLS + col] = y1;
            }
        }
    }
}

// ---- OUT kernel: out = (z @ Wo^T) * gate ----
__global__ __launch_bounds__(256, 2)
void gemm_out(float* __restrict__ Cout) {
    __shared__ float As[3][BM * BK];
    __shared__ float Bs[3][BN * BK];

    const int nloc = (blockIdx.x & 15) * BN;
    const int mloc = (blockIdx.x >> 4) * BM;

    float acc[4][4][4];
#pragma unroll
    for (int i = 0; i < 4; i++)
#pragma unroll
        for (int j = 0; j < 4; j++)
#pragma unroll
            for (int l = 0; l < 4; l++) acc[i][j][l] = 0.0f;

    gemm_mainloop(As, Bs, g_z, CDIM, g_wor, CDIM, mloc, nloc, CDIM, acc);

    const int tid = threadIdx.x;
    const int warp = tid >> 5, lane = tid & 31;
    const int g = lane >> 2, t = lane & 3;
    const int wm = warp & 1, wn = warp >> 1;

#pragma unroll
    for (int mt = 0; mt < 4; mt++) {
#pragma unroll
        for (int nt = 0; nt < 4; nt++) {
            const int row0 = mloc + wm * WM + mt * 16 + g;
            const int col  = nloc + wn * WN + nt * 8 + 2 * t;
            const float* c = acc[mt][nt];
            float2 gt0 = *(const float2*)&g_gate[row0 * HIDDEN + col];
            float2 gt1 = *(const float2*)&g_gate[(row0 + 8) * HIDDEN + col];
            float2 y0, y1;
            y0.x = c[0] * gt0.x; y0.y = c[1] * gt0.y;
            y1.x = c[2] * gt1.x; y1.y = c[3] * gt1.y;
            *(float2*)&Cout[row0 * HIDDEN + col] = y0;
            *(float2*)&Cout[(row0 + 8) * HIDDEN + col] = y1;
        }
    }
}

// ---------------- preround: copy inputs with tf32 (RNA) rounding ----------------
__global__ __launch_bounds__(256)
void preround(const float* __restrict__ hs, const float* __restrict__ Wq,
              const float* __restrict__ Wk, const float* __restrict__ Wv,
              const float* __restrict__ Wo, const float* __restrict__ Wg) {
    constexpr int N_HS = (SEQ * HIDDEN) / 4;          // 1048576
    constexpr int N_W  = (256 * HIDDEN) / 4;          // 131072
    constexpr int TOT  = N_HS * 2 + N_W * 4;          // hs, Wg, Wq, Wk, Wv, Wo

    for (int i = blockIdx.x * blockDim.x + threadIdx.x; i < TOT;
         i += gridDim.x * blockDim.x) {
        const float4* src;
        float4* dst;
        if (i < N_HS) {
            src = (const float4*)hs + i;            dst = (float4*)g_hsr + i;
        } else if (i < 2 * N_HS) {
            src = (const float4*)Wg + (i - N_HS);   dst = (float4*)g_wgr + (i - N_HS);
        } else {
            int j = i - 2 * N_HS;
            if (j < N_W)            { src = (const float4*)Wq + j;           dst = (float4*)g_wqkvr + j; }
            else if (j < 2 * N_W)   { src = (const float4*)Wk + (j - N_W);   dst = (float4*)g_wqkvr + j; }
            else if (j < 3 * N_W)   { src = (const float4*)Wv + (j - 2*N_W); dst = (float4*)g_wqkvr + j; }
            else                    { src = (const float4*)Wo + (j - 3*N_W); dst = (float4*)g_wor + (j - 3*N_W); }
        }
        float4 v = *src;
        v.x = f2tf32(v.x); v.y = f2tf32(v.y); v.z = f2tf32(v.z); v.w = f2tf32(v.w);
        *dst = v;
    }
}

// ---------------- windowed decayed-softmax attention ----------------
// decay 0.45 => bias -0.7985*dist; truncation at W=64 leaves < 1e-21 relative mass.
constexpr int WIN = 64, QB = 128;
constexpr int SROWS = QB + WIN - 1;   // 191
constexpr int PITCH = 9;              // conflict-free scalar smem reads

__global__ __launch_bounds__(128)
void attn_kernel(const float* __restrict__ e0, const float* __restrict__ e1) {
    __shared__ float ks[SROWS * PITCH];
    __shared__ float vs[SROWS * PITCH];

    const int h   = blockIdx.y;
    const int q0  = blockIdx.x * QB;
    const int tid = threadIdx.x;
    const int j0  = q0 - (WIN - 1);

    for (int idx = tid; idx < SROWS * 8; idx += 128) {
        const int r = idx >> 3, c = idx & 7;
        const int j = j0 + r;
        float kv = 0.0f, vv = 0.0f;
        if (j >= 0) {
            kv = g_qkv[j * QKV_COLS + 256 + h * 8 + c];
            vv = g_qkv[j * QKV_COLS + 512 + h * 8 + c];
        }
        ks[r * PITCH + c] = kv;
        vs[r * PITCH + c] = vv;
    }
    __syncthreads();

    const int i = q0 + tid;
    float q[8];
#pragma unroll
    for (int b = 0; b < 8; b++) q[b] = g_qkv[i * QKV_COLS + h * 8 + b];

    float num[8];
#pragma unroll
    for (int b = 0; b < 8; b++) num[b] = 0.0f;
    float den = 0.0f;

    const float LOGD = -0.7985077f;   // ln(0.45)
    const int dmax = (i < WIN - 1) ? i : (WIN - 1);

    for (int d = 0; d <= dmax; d++) {
        const int jj = (tid + (WIN - 1) - d) * PITCH;
        float dot = 0.0f;
#pragma unroll
        for (int b = 0; b < 8; b++) dot += q[b] * ks[jj + b];
        const float w = expf(dot * 0.125f + (float)d * LOGD);
        den += w;
#pragma unroll
        for (int b = 0; b < 8; b++) num[b] += w * vs[jj + b];
    }

    const float inv = 1.0f / den;
#pragma unroll
    for (int b = 0; b < 8; b++) {
        const int c = h * 8 + b;
        const float p = num[b] * inv;
        // write tf32-rounded so gemm_out can consume directly
        g_z[i * CDIM + c] = f2tf32(e1[c] * p + e0[c] * (1.0f - p));
    }
}

// ---------------- launch ----------------
extern "C" void kernel_launch(void* const* d_in, const int* in_sizes, int n_in,
                              void* d_out, int out_size) {
    const float* hs = (const float*)d_in[0];
    const float* Wq = (const float*)d_in[1];
    const float* Wk = (const float*)d_in[2];
    const float* Wv = (const float*)d_in[3];
    const float* Wo = (const float*)d_in[4];
    const float* Wg = (const float*)d_in[5];
    const float* e0 = (const float*)d_in[6];
    const float* e1 = (const float*)d_in[7];
    float* out = (float*)d_out;

    // 0) round all GEMM inputs to tf32 once
    preround<<<1024, 256>>>(hs, Wq, Wk, Wv, Wo, Wg);

    // 1) fused QKV projections (+activations) and gate GEMM (+sigmoid)
    gemm_qkv_gate<<<256 + 96, 256>>>();

    // 2) windowed attention + value-embedding interpolation
    attn_kernel<<<dim3(SEQ / QB, NH), 128>>>(e0, e1);

    // 3) out = (z @ Wo^T) * gate
    gemm_out<<<256, 256>>>(out);
}